// round 6
// baseline (speedup 1.0000x reference)
#include <cuda_runtime.h>
#include <math.h>

#define BATCH 8
#define NPTS  4096
#define DIM   512
#define KC    512
#define OUTD  10

// ---------------- scratch (static device globals; no allocs) ----------------
__device__ float g_buf0[(size_t)BATCH * NPTS * DIM];
__device__ float g_buf1[(size_t)BATCH * NPTS * DIM];
__device__ float g_centers[(size_t)BATCH * KC * DIM];
__device__ float g_x2[BATCH * NPTS];
__device__ float g_c2[BATCH * KC];
__device__ int g_labels[BATCH * NPTS];
__device__ int g_list[BATCH * NPTS];
__device__ int g_counts[BATCH * KC];
__device__ int g_offs[BATCH * KC];
__device__ float g_pooled[BATCH * DIM];

__device__ __forceinline__ float mishf(float x) {
    float sp = fmaxf(x, 0.0f) + log1pf(expf(-fabsf(x)));
    return x * tanhf(sp);
}

__device__ __forceinline__ void ffma2(unsigned long long& d, unsigned long long a,
                                      unsigned long long b) {
    asm("fma.rn.f32x2 %0, %1, %2, %0;" : "+l"(d) : "l"(a), "l"(b));
}
__device__ __forceinline__ unsigned long long dup2(unsigned x) {
    unsigned long long r;
    asm("mov.b64 %0, {%1, %1};" : "=l"(r) : "r"(x));
    return r;
}

// ---------------- fused: x2 for all rows; centers0 + c2 for first KC rows ---
__global__ void rowsq_init_kernel(const float* __restrict__ X) {
    int b = blockIdx.y, i = blockIdx.x, t = threadIdx.x;  // 128 threads
    const float* row = X + ((size_t)b * NPTS + i) * DIM;
    bool isC = (i < KC);
    float* crow = g_centers + ((size_t)b * KC + i) * DIM;
    float s = 0.f;
#pragma unroll
    for (int u = 0; u < 4; u++) {
        float v = row[t + 128 * u];
        if (isC) crow[t + 128 * u] = v;
        s += v * v;
    }
    for (int o = 16; o > 0; o >>= 1) s += __shfl_down_sync(0xffffffffu, s, o);
    __shared__ float w[4];
    if ((t & 31) == 0) w[t >> 5] = s;
    __syncthreads();
    if (t == 0) {
        float tot = w[0] + w[1] + w[2] + w[3];
        g_x2[b * NPTS + i] = tot;
        if (isC) g_c2[b * KC + i] = tot;
    }
}

// ============================================================================
// f32x2 GEMM core v3: 128x128 tile, BK=8, 128 threads, 16x8 micro-tile,
// internal loop over all N-tiles (grid = M-tiles x batch only).
// MODE 0: assign -> writes argmin labels directly (no global atomics/reset)
// MODE 1: C = A@B (B is KxN) plain store
// MODE 2: pooled mish epilogue (bias + mish + column sum into g_pooled)
// ============================================================================
template <int MODE>
__global__ __launch_bounds__(128, 2) void gemm_kernel(
    const float* __restrict__ A, const float* __restrict__ B,
    float* __restrict__ C, const float* __restrict__ bias,
    int Kd, int Nn, size_t aBatch, size_t bBatch, size_t cBatch) {
    __shared__ __align__(16) float As[2][8][128];
    __shared__ __align__(16) float Bs[2][8][128];
    __shared__ unsigned long long skey[128];
    __shared__ float colsum[128];

    int b = blockIdx.z;
    const float* Ab = A + (size_t)b * aBatch;
    const float* Bb = B + (size_t)b * bBatch;
    int m0 = blockIdx.x * 128;
    int tid = threadIdx.x;
    int tx = tid & 15, ty = tid >> 4;

    int ar = tid >> 1, akq = (tid & 1) * 4;   // A / transposed-B mapping
    int bkr = tid >> 5, bc4 = (tid & 31) * 4;  // natural B (KxN) mapping

    float4 ra0, ra1, rb0, rb1;

    auto loadT = [&](int k0, int n0) {
        ra0 = *(const float4*)(Ab + (size_t)(m0 + ar) * Kd + k0 + akq);
        ra1 = *(const float4*)(Ab + (size_t)(m0 + ar + 64) * Kd + k0 + akq);
        if (MODE == 0) {
            rb0 = *(const float4*)(Bb + (size_t)(n0 + ar) * Kd + k0 + akq);
            rb1 = *(const float4*)(Bb + (size_t)(n0 + ar + 64) * Kd + k0 + akq);
        } else {
            rb0 = *(const float4*)(Bb + (size_t)(k0 + bkr) * Nn + n0 + bc4);
            rb1 = *(const float4*)(Bb + (size_t)(k0 + bkr + 4) * Nn + n0 + bc4);
        }
    };
    auto storeT = [&](int s) {
#pragma unroll
        for (int j = 0; j < 4; j++) {
            As[s][akq + j][ar] = (&ra0.x)[j];
            As[s][akq + j][ar + 64] = (&ra1.x)[j];
        }
        if (MODE == 0) {
#pragma unroll
            for (int j = 0; j < 4; j++) {
                Bs[s][akq + j][ar] = (&rb0.x)[j];
                Bs[s][akq + j][ar + 64] = (&rb1.x)[j];
            }
        } else {
            *(float4*)&Bs[s][bkr][bc4] = rb0;
            *(float4*)&Bs[s][bkr + 4][bc4] = rb1;
        }
    };

    if (MODE == 0) skey[tid] = 0xFFFFFFFFFFFFFFFFull;

    int nk = Kd >> 3;
    int ntiles = Nn >> 7;
    for (int nt = 0; nt < ntiles; nt++) {
        int n0 = nt << 7;
        unsigned long long acc[8][8];
#pragma unroll
        for (int i = 0; i < 8; i++)
#pragma unroll
            for (int j = 0; j < 8; j++) acc[i][j] = 0ull;

        loadT(0, n0);
        storeT(0);
        __syncthreads();

        int s = 0;
        for (int t = 0; t < nk; t++) {
            if (t + 1 < nk) loadT((t + 1) << 3, n0);
#pragma unroll
            for (int kk = 0; kk < 8; kk++) {
                const ulonglong2* apv = (const ulonglong2*)&As[s][kk][ty * 16];
                ulonglong2 A0 = apv[0], A1 = apv[1], A2 = apv[2], A3 = apv[3];
                uint4 b0 = *(const uint4*)&Bs[s][kk][tx * 8];
                uint4 b1 = *(const uint4*)&Bs[s][kk][tx * 8 + 4];
                unsigned long long ap[8] = {A0.x, A0.y, A1.x, A1.y,
                                            A2.x, A2.y, A3.x, A3.y};
                unsigned long long bd[8] = {dup2(b0.x), dup2(b0.y), dup2(b0.z),
                                            dup2(b0.w), dup2(b1.x), dup2(b1.y),
                                            dup2(b1.z), dup2(b1.w)};
#pragma unroll
                for (int i = 0; i < 8; i++)
#pragma unroll
                    for (int j = 0; j < 8; j++) ffma2(acc[i][j], ap[i], bd[j]);
            }
            if (t + 1 < nk) {
                storeT(s ^ 1);
                __syncthreads();
                s ^= 1;
            }
        }

        if (MODE == 0) {
            float c2v[8];
#pragma unroll
            for (int j = 0; j < 8; j++) c2v[j] = g_c2[b * KC + n0 + tx * 8 + j];
            float x2v[16];
#pragma unroll
            for (int i = 0; i < 16; i++)
                x2v[i] = g_x2[b * NPTS + m0 + ty * 16 + i];
#pragma unroll
            for (int mp = 0; mp < 8; mp++) {
#pragma unroll
                for (int h = 0; h < 2; h++) {
                    int rl = ty * 16 + 2 * mp + h;
                    unsigned long long best = 0xFFFFFFFFFFFFFFFFull;
#pragma unroll
                    for (int j = 0; j < 8; j++) {
                        float dot = ((const float*)&acc[mp][j])[h];
                        float d = (x2v[2 * mp + h] + c2v[j]) - 2.0f * dot;
                        unsigned u = __float_as_uint(d);
                        u = (u & 0x80000000u) ? ~u : (u | 0x80000000u);
                        unsigned long long key =
                            ((unsigned long long)u << 32) |
                            (unsigned)(n0 + tx * 8 + j);
                        best = (key < best) ? key : best;
                    }
                    atomicMin(&skey[rl], best);
                }
            }
        } else if (MODE == 1) {
            float* Cb = C + (size_t)b * cBatch;
#pragma unroll
            for (int mp = 0; mp < 8; mp++) {
#pragma unroll
                for (int h = 0; h < 2; h++) {
                    float* p = Cb + (size_t)(m0 + ty * 16 + 2 * mp + h) * Nn +
                               n0 + tx * 8;
                    float4 v0, v1;
#pragma unroll
                    for (int j = 0; j < 4; j++) {
                        (&v0.x)[j] = ((const float*)&acc[mp][j])[h];
                        (&v1.x)[j] = ((const float*)&acc[mp][j + 4])[h];
                    }
                    *(float4*)p = v0;
                    *(float4*)(p + 4) = v1;
                }
            }
        } else {
            colsum[tid] = 0.f;
            float bj[8];
#pragma unroll
            for (int j = 0; j < 8; j++) bj[j] = bias[n0 + tx * 8 + j];
            __syncthreads();
            float part[8] = {0, 0, 0, 0, 0, 0, 0, 0};
#pragma unroll
            for (int mp = 0; mp < 8; mp++)
#pragma unroll
                for (int j = 0; j < 8; j++) {
                    part[j] += mishf(((const float*)&acc[mp][j])[0] + bj[j]);
                    part[j] += mishf(((const float*)&acc[mp][j])[1] + bj[j]);
                }
#pragma unroll
            for (int j = 0; j < 8; j++) atomicAdd(&colsum[tx * 8 + j], part[j]);
            __syncthreads();
            atomicAdd(&g_pooled[b * DIM + n0 + tid], colsum[tid]);
        }
        __syncthreads();  // smem reuse + skey visibility for next tile / final
    }

    if (MODE == 0)
        g_labels[b * NPTS + m0 + tid] = (int)(skey[tid] & 0xFFFFFFFFu);
}

// ---------------- parallel stable member-list build (counting sort) ---------
// 8 chunks of 512 elems; per-chunk histogram -> label scan -> chunk-prefixed
// cursors -> all 8 warps scatter their chunk concurrently in stable order.
__global__ __launch_bounds__(256) void listbuild_kernel() {
    __shared__ int labs[NPTS];     // 16KB
    __shared__ int cnt[8][KC];     // 16KB: counts -> chunk start cursors
    __shared__ int tot[KC];
    __shared__ int offs[KC];
    int b = blockIdx.x, t = threadIdx.x;
    int w = t >> 5, lane = t & 31;

    for (int idx = t; idx < 8 * KC; idx += 256) ((int*)cnt)[idx] = 0;
    for (int i = t; i < NPTS; i += 256) labs[i] = g_labels[b * NPTS + i];
    __syncthreads();

    // per-chunk histogram: warp w counts chunk w
    for (int r = 0; r < 16; r++) {
        int i = w * 512 + r * 32 + lane;
        atomicAdd(&cnt[w][labs[i]], 1);
    }
    __syncthreads();

    // per-label prefix over chunks; tot = per-label count
    for (int l = t; l < KC; l += 256) {
        int s = 0;
#pragma unroll
        for (int ch = 0; ch < 8; ch++) {
            int c = cnt[ch][l];
            cnt[ch][l] = s;
            s += c;
        }
        tot[l] = s;
    }
    __syncthreads();

    // exclusive scan of tot -> offs (warp 0)
    if (t < 32) {
        int carry = 0;
        for (int c = 0; c < KC / 32; c++) {
            int v = tot[c * 32 + t];
            int x = v;
#pragma unroll
            for (int o = 1; o < 32; o <<= 1) {
                int y = __shfl_up_sync(0xffffffffu, x, o);
                if (t >= o) x += y;
            }
            offs[c * 32 + t] = carry + x - v;
            carry += __shfl_sync(0xffffffffu, x, 31);
        }
    }
    __syncthreads();
    for (int l = t; l < KC; l += 256) {
        g_counts[b * KC + l] = tot[l];
        g_offs[b * KC + l] = offs[l];
    }
    for (int idx = t; idx < 8 * KC; idx += 256) {
        int ch = idx >> 9, l = idx & (KC - 1);
        cnt[ch][l] += offs[l];
    }
    __syncthreads();

    // stable scatter: warp w handles chunk w, 16 sequential rounds
    unsigned below = (lane == 0) ? 0u : (0xffffffffu >> (32 - lane));
    for (int r = 0; r < 16; r++) {
        int i = w * 512 + r * 32 + lane;
        int l = labs[i];
        unsigned mask = __match_any_sync(0xffffffffu, l);
        int base = cnt[w][l];
        __syncwarp();
        int rank = __popc(mask & below);
        g_list[b * NPTS + base + rank] = i;
        if (lane == __ffs(mask) - 1) cnt[w][l] = base + __popc(mask);
        __syncwarp();
    }
}

// ---------------- center update: gather listed members (ascending order) ----
__global__ void gather_update_kernel(const float* __restrict__ X) {
    int b = blockIdx.y, k = blockIdx.x, t = threadIdx.x;  // 128 threads
    int cnt = g_counts[b * KC + k];
    int off = g_offs[b * KC + k];
    const int* lst = g_list + b * NPTS + off;
    const float* Xb = X + (size_t)b * NPTS * DIM;
    float a0 = 0, a1 = 0, a2 = 0, a3 = 0;
    for (int e = 0; e < cnt; e++) {
        const float* xr = Xb + (size_t)lst[e] * DIM;
        a0 += xr[t]; a1 += xr[t + 128]; a2 += xr[t + 256]; a3 += xr[t + 384];
    }
    float* crow = g_centers + ((size_t)b * KC + k) * DIM;
    float v0, v1, v2, v3;
    if (cnt > 0) {
        float cf = (float)cnt;
        v0 = a0 / cf; v1 = a1 / cf; v2 = a2 / cf; v3 = a3 / cf;
        crow[t] = v0; crow[t + 128] = v1; crow[t + 256] = v2; crow[t + 384] = v3;
    } else {
        v0 = crow[t]; v1 = crow[t + 128]; v2 = crow[t + 256]; v3 = crow[t + 384];
    }
    float sq = v0 * v0 + v1 * v1 + v2 * v2 + v3 * v3;
    for (int o = 16; o > 0; o >>= 1) sq += __shfl_down_sync(0xffffffffu, sq, o);
    __shared__ float w[4];
    if ((t & 31) == 0) w[t >> 5] = sq;
    __syncthreads();
    if (t == 0) g_c2[b * KC + k] = w[0] + w[1] + w[2] + w[3];
}

// ---------------- h_next = mish(adj @ one_hot(labels)), 16 rows/block -------
__global__ __launch_bounds__(256) void segsum_mish_kernel(const float* __restrict__ adj,
                                                          float* __restrict__ Hout) {
    int b = blockIdx.y, i0 = blockIdx.x * 16, t = threadIdx.x;  // 256 threads
    __shared__ float acc[16][KC];            // 32KB
    __shared__ unsigned short labs[NPTS];    // 8KB
    const int* lb = g_labels + b * NPTS;
    for (int j = t; j < NPTS; j += 256) labs[j] = (unsigned short)lb[j];
#pragma unroll
    for (int r = 0; r < 16; r++)
        for (int k = t; k < KC; k += 256) acc[r][k] = 0.f;
    __syncthreads();
#pragma unroll
    for (int r = 0; r < 16; r++) {
        const float* arow = adj + ((size_t)b * NPTS + i0 + r) * NPTS;
        for (int j = t; j < NPTS; j += 256) atomicAdd(&acc[r][labs[j]], arow[j]);
    }
    __syncthreads();
#pragma unroll
    for (int r = 0; r < 16; r++) {
        float* hrow = Hout + ((size_t)b * NPTS + i0 + r) * DIM;
        for (int k = t; k < KC; k += 256) hrow[k] = mishf(acc[r][k]);
    }
}

__global__ void zero_pooled_kernel() {
    g_pooled[blockIdx.x * DIM + threadIdx.x] = 0.f;
}

// ---------------- out = pooled @ Wp + bp ----------------
__global__ void out_kernel(const float* __restrict__ Wp, const float* __restrict__ bp,
                           float* __restrict__ out) {
    int b = blockIdx.x, t = threadIdx.x;  // 32 threads
    if (t < OUTD) {
        const float* p = g_pooled + b * DIM;
        float s = 0.f;
        for (int h = 0; h < DIM; h++) s += p[h] * Wp[h * OUTD + t];
        out[b * OUTD + t] = s + bp[t];
    }
}

// ---------------- host orchestration ----------------
static void run_ctod(const float* X, const float* centers) {
    rowsq_init_kernel<<<dim3(NPTS, BATCH), 128>>>(X);
    for (int it = 0; it < 10; it++) {
        gemm_kernel<0><<<dim3(NPTS / 128, 1, BATCH), 128>>>(
            X, centers, nullptr, nullptr, DIM, KC,
            (size_t)NPTS * DIM, (size_t)KC * DIM, (size_t)0);
        if (it < 9) {
            listbuild_kernel<<<BATCH, 256>>>();
            gather_update_kernel<<<dim3(KC, BATCH), 128>>>(X);
        }
    }
}

extern "C" void kernel_launch(void* const* d_in, const int* in_sizes, int n_in,
                              void* d_out, int out_size) {
    const float* x   = (const float*)d_in[0];
    const float* adj = (const float*)d_in[1];
    const float* W   = (const float*)d_in[2];
    const float* bb  = (const float*)d_in[3];
    const float* Wp  = (const float*)d_in[4];
    const float* bp  = (const float*)d_in[5];
    float* out = (float*)d_out;

    float *h0, *h1, *centers;
    cudaGetSymbolAddress((void**)&h0, g_buf0);
    cudaGetSymbolAddress((void**)&h1, g_buf1);
    cudaGetSymbolAddress((void**)&centers, g_centers);

    // Layer 1
    run_ctod(x, centers);
    segsum_mish_kernel<<<dim3(NPTS / 16, BATCH), 256>>>(adj, h0);
    // Layer 2
    run_ctod(h0, centers);
    segsum_mish_kernel<<<dim3(NPTS / 16, BATCH), 256>>>(adj, h1);
    // Layer 3
    run_ctod(h1, centers);
    segsum_mish_kernel<<<dim3(NPTS / 16, BATCH), 256>>>(adj, h0);

    // Final layer: t = h0 @ W, then pooled mish(adj @ t + b)
    gemm_kernel<1><<<dim3(NPTS / 128, 1, BATCH), 128>>>(
        h0, W, h1, nullptr, DIM, DIM,
        (size_t)NPTS * DIM, (size_t)0, (size_t)NPTS * DIM);
    zero_pooled_kernel<<<BATCH, DIM>>>();
    gemm_kernel<2><<<dim3(NPTS / 128, 1, BATCH), 128>>>(
        adj, h1, nullptr, bb, NPTS, DIM,
        (size_t)NPTS * NPTS, (size_t)NPTS * DIM, (size_t)0);
    out_kernel<<<BATCH, 32>>>(Wp, bp, out);
}